// round 2
// baseline (speedup 1.0000x reference)
#include <cuda_runtime.h>
#include <math.h>

// Problem constants (fixed by the dataset)
#define BATCH 128
#define TSTEPS 128
#define DIM 1024
#define NCOLS 2048           // [r-block | u-block] concatenated output features
#define KSPLIT 8             // K-split factor for the per-step GEMM

// ---------------- scratch (static device globals; no cudaMalloc) ----------
__device__ float g_FW[(size_t)BATCH * TSTEPS * NCOLS];   // [B*T][2048]  fWr||fW   (128 MB)
__device__ float g_part[KSPLIT * BATCH * NCOLS];         // [8][128][2048] partials (8 MB)
__device__ float g_h[BATCH * DIM];                       // current hidden state    (512 KB)

// ---------------- f32x2 packed-FMA helpers (Blackwell FFMA2) --------------
__device__ __forceinline__ unsigned long long pack2(float x, float y) {
    unsigned long long r;
    asm("mov.b64 %0, {%1, %2};" : "=l"(r) : "f"(x), "f"(y));
    return r;
}
__device__ __forceinline__ unsigned long long fma2(unsigned long long a,
                                                   unsigned long long b,
                                                   unsigned long long c) {
    unsigned long long d;
    asm("fma.rn.f32x2 %0, %1, %2, %3;" : "=l"(d) : "l"(a), "l"(b), "l"(c));
    return d;
}
__device__ __forceinline__ float2 unpack2(unsigned long long v) {
    float2 f;
    asm("mov.b64 {%0, %1}, %2;" : "=f"(f.x), "=f"(f.y) : "l"(v));
    return f;
}

// ---------------------------------------------------------------------------
// NT GEMM: C[m][n] = sum_k A[m][k] * B[n][k]
//   A: row-major [M][1024]; B: virtual concat of B0 (rows 0..1023) and
//   B1 (rows 1024..2047), each row-major [1024][1024].
//   Tile 128x128, BK=16, 256 threads, 8x8 micro-tile, f32x2 accumulators.
//   grid = (16 n-tiles, m-tiles, k-splits).  k0 = z*kiters*16.
//   mode 0: A = Ain (facts),  C = g_FW   (precompute, z = 0)
//   mode 1: A = g_h,          C = g_part (per-step, z = 0..7)
// ---------------------------------------------------------------------------
__global__ __launch_bounds__(256) void gemm_nt(const float* __restrict__ Ain,
                                               const float* __restrict__ B0,
                                               const float* __restrict__ B1,
                                               int kiters, int mode) {
    __shared__ float As[16][132];   // stride 132 floats = 528 B (16B aligned)
    __shared__ float Bs[16][132];

    const float* A = (mode == 0) ? Ain : g_h;
    float* C       = (mode == 0) ? g_FW : g_part;

    const int m0 = blockIdx.y * 128;
    const int nt = blockIdx.x;                 // n-tile index (0..15)
    const float* Bmat = (nt < 8) ? (B0 + (size_t)nt * 128 * DIM)
                                 : (B1 + (size_t)(nt - 8) * 128 * DIM);
    const int k0 = blockIdx.z * kiters * 16;

    const int tid = threadIdx.x;
    const int lr  = tid >> 2;                  // load row 0..63
    const int lc  = (tid & 3) * 4;             // load col (floats) 0,4,8,12
    const int tx  = tid & 15;                  // micro-tile n
    const int ty  = tid >> 4;                  // micro-tile m

    unsigned long long acc[8][4];
#pragma unroll
    for (int i = 0; i < 8; ++i)
#pragma unroll
        for (int j = 0; j < 4; ++j) acc[i][j] = 0ull;

    for (int kt = 0; kt < kiters; ++kt) {
        const int kb = k0 + kt * 16;
#pragma unroll
        for (int p = 0; p < 2; ++p) {
            const int row = lr + p * 64;
            float4 va = *(const float4*)(A + (size_t)(m0 + row) * DIM + kb + lc);
            As[lc + 0][row] = va.x;
            As[lc + 1][row] = va.y;
            As[lc + 2][row] = va.z;
            As[lc + 3][row] = va.w;
            float4 vb = *(const float4*)(Bmat + (size_t)row * DIM + kb + lc);
            Bs[lc + 0][row] = vb.x;
            Bs[lc + 1][row] = vb.y;
            Bs[lc + 2][row] = vb.z;
            Bs[lc + 3][row] = vb.w;
        }
        __syncthreads();

#pragma unroll
        for (int kk = 0; kk < 16; ++kk) {
            float4 a0 = *(const float4*)&As[kk][ty * 8];
            float4 a1 = *(const float4*)&As[kk][ty * 8 + 4];
            const unsigned long long* bq =
                (const unsigned long long*)&Bs[kk][tx * 8];
            unsigned long long b0 = bq[0], b1 = bq[1], b2 = bq[2], b3 = bq[3];
            float av[8] = {a0.x, a0.y, a0.z, a0.w, a1.x, a1.y, a1.z, a1.w};
#pragma unroll
            for (int i = 0; i < 8; ++i) {
                unsigned long long ad = pack2(av[i], av[i]);
                acc[i][0] = fma2(ad, b0, acc[i][0]);
                acc[i][1] = fma2(ad, b1, acc[i][1]);
                acc[i][2] = fma2(ad, b2, acc[i][2]);
                acc[i][3] = fma2(ad, b3, acc[i][3]);
            }
        }
        __syncthreads();
    }

    // epilogue
    const size_t crowbase = (size_t)blockIdx.z * gridDim.y * 128;
#pragma unroll
    for (int i = 0; i < 8; ++i) {
        float2 p0 = unpack2(acc[i][0]);
        float2 p1 = unpack2(acc[i][1]);
        float2 p2 = unpack2(acc[i][2]);
        float2 p3 = unpack2(acc[i][3]);
        float4 o0 = make_float4(p0.x, p0.y, p1.x, p1.y);
        float4 o1 = make_float4(p2.x, p2.y, p3.x, p3.y);
        float* cp = C + (crowbase + m0 + ty * 8 + i) * NCOLS + nt * 128 + tx * 8;
        *(float4*)cp = o0;
        *(float4*)(cp + 4) = o1;
    }
}

// ---------------------------------------------------------------------------
// init: h <- mem_old[:,0,:]
// ---------------------------------------------------------------------------
__global__ void init_h_kernel(const float* __restrict__ mem_old) {
    int i = blockIdx.x * blockDim.x + threadIdx.x;
    g_h[i] = mem_old[i];
}

// ---------------------------------------------------------------------------
// combine: reduce K-split partials, apply GRU-style gate, update h in place,
// and scatter to the output at t == num_facts[b]-1.
//   r   = sigmoid(fWr_t + h@Ur_w^T + Ur_b)
//   h_t = tanh(fW_t + r * (h@U_w^T + U_b))
//   h'  = g_t * h_t + (1-g_t) * h
// ---------------------------------------------------------------------------
__global__ void combine_kernel(const float* __restrict__ g,
                               const float* __restrict__ Urb,
                               const float* __restrict__ Ub,
                               const int* __restrict__ nf,
                               float* __restrict__ out, int t) {
    int idx = blockIdx.x * blockDim.x + threadIdx.x;  // 0..131071
    int b = idx >> 10;
    int d = idx & 1023;

    float pr = 0.f, pu = 0.f;
#pragma unroll
    for (int s = 0; s < KSPLIT; ++s) {
        const float* pb = g_part + ((size_t)s * BATCH + b) * NCOLS;
        pr += pb[d];
        pu += pb[1024 + d];
    }
    const float* fw = g_FW + ((size_t)b * TSTEPS + t) * NCOLS;
    float xr = fw[d] + pr + Urb[d];
    float r  = 1.f / (1.f + expf(-xr));
    float up = pu + Ub[d];
    float ht = tanhf(fw[1024 + d] + r * up);
    float gt = g[b * TSTEPS + t];
    float hold = g_h[idx];
    float hn = gt * ht + (1.f - gt) * hold;
    g_h[idx] = hn;
    if (t == nf[b] - 1) out[idx] = hn;
}

// ---------------------------------------------------------------------------
extern "C" void kernel_launch(void* const* d_in, const int* in_sizes, int n_in,
                              void* d_out, int out_size) {
    const float* facts   = (const float*)d_in[0];  // [128,128,1024]
    const int*   nf      = (const int*)d_in[1];    // [128]
    const float* g       = (const float*)d_in[2];  // [128,128,1]
    const float* mem_old = (const float*)d_in[3];  // [128,1,1024]
    const float* Wr      = (const float*)d_in[4];  // [1024,1024]
    const float* Urw     = (const float*)d_in[5];
    const float* Urb     = (const float*)d_in[6];  // [1024]
    const float* W       = (const float*)d_in[7];
    const float* Uw      = (const float*)d_in[8];
    const float* Ub      = (const float*)d_in[9];
    float* out = (float*)d_out;

    // h <- mem_old
    init_h_kernel<<<(BATCH * DIM) / 256, 256>>>(mem_old);

    // Precompute fWr||fW : C[16384,2048] = facts @ [Wr;W]^T
    gemm_nt<<<dim3(16, 128, 1), 256>>>(facts, Wr, W, /*kiters=*/64, /*mode=*/0);

    // Sequential scan
    for (int t = 0; t < TSTEPS; ++t) {
        gemm_nt<<<dim3(16, 1, KSPLIT), 256>>>(nullptr, Urw, Uw,
                                              /*kiters=*/DIM / (KSPLIT * 16),
                                              /*mode=*/1);
        combine_kernel<<<(BATCH * DIM) / 256, 256>>>(g, Urb, Ub, nf, out, t);
    }
}

// round 9
// speedup vs baseline: 1.6052x; 1.6052x over previous
#include <cuda_runtime.h>
#include <cuda_bf16.h>
#include <mma.h>
#include <math.h>
#include <stdint.h>

using namespace nvcuda;

// Problem constants (fixed by the dataset)
#define BATCH  128
#define TSTEPS 128
#define DIM    1024
#define NCOLS  2048          // [r-block | u-block] output features
#define KP     3072          // packed K' = [hi|hi|lo] x [hi|lo|hi] split GEMM
#define KSPLIT 8             // K-split factor for the per-step GEMM
#define NCHUNK 96            // KP / 32

// GEMM tiling
#define BM 128
#define BN 64
#define BK 32
#define LDA 40               // smem leading dim (bf16 elems), mult of 8
#define LDB 40
#define ASZ (BM * LDA)
#define BSZ (BN * LDB)

// ---------------- scratch (static device globals; no cudaMalloc) ----------
// NOTE: these symbols are ONLY referenced inside device code. Passing them
// as kernel arguments from host code is UB (host shadow address) — that was
// the rounds-4..8 bug.
__device__ float g_FW[(size_t)BATCH * TSTEPS * NCOLS];      // fWr||fW (128 MB)
__device__ float g_part[KSPLIT * BATCH * NCOLS];            // k-split partials
__device__ float g_h[BATCH * DIM];                          // hidden state
__device__ __align__(16) __nv_bfloat16 g_Af[(size_t)BATCH * TSTEPS * KP]; // packed facts
__device__ __align__(16) __nv_bfloat16 g_Ah[BATCH * KP];                  // packed h
__device__ __align__(16) __nv_bfloat16 g_Bf[(size_t)NCOLS * KP];          // packed [Wr;W]
__device__ __align__(16) __nv_bfloat16 g_Bu[(size_t)NCOLS * KP];          // packed [Urw;Uw]

// ---------------- helpers ---------------------------------------------------
__device__ __forceinline__ uint32_t smem_u32(const void* p) {
    uint32_t a;
    asm("{ .reg .u64 t; cvta.to.shared.u64 t, %1; cvt.u32.u64 %0, t; }"
        : "=r"(a) : "l"(p));
    return a;
}

__device__ __forceinline__ void cpasync16(uint32_t dst, const void* src) {
    asm volatile("cp.async.cg.shared.global [%0], [%1], 16;"
                 :: "r"(dst), "l"(src) : "memory");
}

// stage one BK x (BM A-rows + BN B-rows) chunk into smem (row-major, padded)
__device__ __forceinline__ void stage_tiles(
    const __nv_bfloat16* __restrict__ A, const __nv_bfloat16* __restrict__ Bw,
    uint32_t sa_base, uint32_t sb_base, int m0, int n0, int kb, int tid) {
#pragma unroll
    for (int i = 0; i < 4; ++i) {          // A: 128 rows x 32k = 512 x 16B
        int v = tid + 128 * i;
        int row = v >> 2, kv = v & 3;
        cpasync16(sa_base + row * (LDA * 2) + kv * 16,
                  A + (size_t)(m0 + row) * KP + kb + kv * 8);
    }
#pragma unroll
    for (int i = 0; i < 2; ++i) {          // B: 64 rows x 32k = 256 x 16B
        int v = tid + 128 * i;
        int row = v >> 2, kv = v & 3;
        cpasync16(sb_base + row * (LDB * 2) + kv * 16,
                  Bw + (size_t)(n0 + row) * KP + kb + kv * 8);
    }
    asm volatile("cp.async.commit_group;" ::: "memory");
}

// ---------------------------------------------------------------------------
// wmma bf16-split NT GEMM: C[m][n] = sum_k A'[m][k] * B'[n][k], fp32 accum.
//   mode 0: A=g_Af [16384][KP], B=g_Bf, C=g_FW   (precompute)
//   mode 1: A=g_Ah [128][KP],   B=g_Bu, C=g_part (per-step, k-split via z)
//   CTA 128x64, 4 warps (2x2), warp tile 64x32 (4x2 wmma 16x16x16 frags),
//   BK=32, cp.async double buffering.
//   grid = (32 n-tiles, m-tiles, k-splits); C row base = z*gridDim.y*BM.
// ---------------------------------------------------------------------------
__global__ __launch_bounds__(128) void gemm_wmma(int mode, int kchunks) {
    __shared__ __align__(16) __nv_bfloat16 sa[2][ASZ];
    __shared__ __align__(16) __nv_bfloat16 sb[2][BSZ];

    const __nv_bfloat16* A  = (mode == 0) ? g_Af : g_Ah;
    const __nv_bfloat16* Bw = (mode == 0) ? g_Bf : g_Bu;
    float* C                = (mode == 0) ? g_FW : g_part;

    const int tid = threadIdx.x, warp = tid >> 5;
    const int wm = warp >> 1, wn = warp & 1;
    const int m0 = blockIdx.y * BM, n0 = blockIdx.x * BN;
    const int kb0 = blockIdx.z * kchunks * BK;
    const uint32_t sa0 = smem_u32(&sa[0][0]);
    const uint32_t sb0 = smem_u32(&sb[0][0]);

    wmma::fragment<wmma::accumulator, 16, 16, 16, float> c[4][2];
#pragma unroll
    for (int mt = 0; mt < 4; ++mt)
#pragma unroll
        for (int nt = 0; nt < 2; ++nt) wmma::fill_fragment(c[mt][nt], 0.0f);

    stage_tiles(A, Bw, sa0, sb0, m0, n0, kb0, tid);

    for (int kt = 0; kt < kchunks; ++kt) {
        if (kt + 1 < kchunks) {
            stage_tiles(A, Bw, sa0 + ((kt + 1) & 1) * (ASZ * 2),
                        sb0 + ((kt + 1) & 1) * (BSZ * 2),
                        m0, n0, kb0 + (kt + 1) * BK, tid);
            asm volatile("cp.async.wait_group 1;" ::: "memory");
        } else {
            asm volatile("cp.async.wait_group 0;" ::: "memory");
        }
        __syncthreads();

        const __nv_bfloat16* pa = &sa[kt & 1][0] + (wm * 64) * LDA;
        const __nv_bfloat16* pb = &sb[kt & 1][0] + (wn * 32) * LDB;
#pragma unroll
        for (int kk = 0; kk < 2; ++kk) {
            wmma::fragment<wmma::matrix_a, 16, 16, 16, __nv_bfloat16,
                           wmma::row_major> af[4];
            wmma::fragment<wmma::matrix_b, 16, 16, 16, __nv_bfloat16,
                           wmma::col_major> bf[2];
#pragma unroll
            for (int mt = 0; mt < 4; ++mt)
                wmma::load_matrix_sync(af[mt], pa + mt * 16 * LDA + kk * 16, LDA);
#pragma unroll
            for (int nt = 0; nt < 2; ++nt)
                wmma::load_matrix_sync(bf[nt], pb + nt * 16 * LDB + kk * 16, LDB);
#pragma unroll
            for (int mt = 0; mt < 4; ++mt)
#pragma unroll
                for (int nt = 0; nt < 2; ++nt)
                    wmma::mma_sync(c[mt][nt], af[mt], bf[nt], c[mt][nt]);
        }
        __syncthreads();
    }

    const size_t crow = (size_t)blockIdx.z * gridDim.y * BM + m0 + wm * 64;
    const int ccol = n0 + wn * 32;
#pragma unroll
    for (int mt = 0; mt < 4; ++mt)
#pragma unroll
        for (int nt = 0; nt < 2; ++nt)
            wmma::store_matrix_sync(C + (crow + mt * 16) * NCOLS + ccol + nt * 16,
                                    c[mt][nt], NCOLS, wmma::mem_row_major);
}

// ---------------------------------------------------------------------------
// packing kernels: fp32 -> bf16 hi/lo split concat along K
//   A' = [hi | hi | lo],  B' = [hi | lo | hi]
// ---------------------------------------------------------------------------
__global__ void pack_w_kernel(const float* __restrict__ w0,
                              const float* __restrict__ w1, int which) {
    __nv_bfloat16* dst = (which == 0) ? g_Bf : g_Bu;
    size_t i = (size_t)blockIdx.x * blockDim.x + threadIdx.x;  // 2048*1024
    int n = (int)(i >> 10), k = (int)(i & 1023);
    float v = (n < 1024) ? w0[(size_t)n * 1024 + k] : w1[(size_t)(n - 1024) * 1024 + k];
    __nv_bfloat16 hi = __float2bfloat16(v);
    __nv_bfloat16 lo = __float2bfloat16(v - __bfloat162float(hi));
    __nv_bfloat16* row = dst + (size_t)n * KP;
    row[k] = hi; row[1024 + k] = lo; row[2048 + k] = hi;
}

__global__ void pack_facts_kernel(const float* __restrict__ facts) {
    size_t i = (size_t)blockIdx.x * blockDim.x + threadIdx.x;  // 16384*1024
    size_t r = i >> 10; int k = (int)(i & 1023);
    float v = facts[i];
    __nv_bfloat16 hi = __float2bfloat16(v);
    __nv_bfloat16 lo = __float2bfloat16(v - __bfloat162float(hi));
    __nv_bfloat16* row = g_Af + r * KP;
    row[k] = hi; row[1024 + k] = hi; row[2048 + k] = lo;
}

__global__ void init_h_kernel(const float* __restrict__ mem_old) {
    int i = blockIdx.x * blockDim.x + threadIdx.x;  // 131072
    float v = mem_old[i];
    g_h[i] = v;
    int b = i >> 10, d = i & 1023;
    __nv_bfloat16 hi = __float2bfloat16(v);
    __nv_bfloat16 lo = __float2bfloat16(v - __bfloat162float(hi));
    __nv_bfloat16* row = g_Ah + (size_t)b * KP;
    row[d] = hi; row[1024 + d] = hi; row[2048 + d] = lo;
}

// ---------------------------------------------------------------------------
// combine: reduce K-split partials, GRU gate, update h (+ bf16 repack), out
// ---------------------------------------------------------------------------
__global__ void combine_kernel(const float* __restrict__ g,
                               const float* __restrict__ Urb,
                               const float* __restrict__ Ub,
                               const int* __restrict__ nf,
                               float* __restrict__ out, int t) {
    int idx = blockIdx.x * blockDim.x + threadIdx.x;  // 0..131071
    int b = idx >> 10;
    int d = idx & 1023;

    float pr = 0.f, pu = 0.f;
#pragma unroll
    for (int s = 0; s < KSPLIT; ++s) {
        const float* pb = g_part + ((size_t)s * BATCH + b) * NCOLS;
        pr += pb[d];
        pu += pb[1024 + d];
    }
    const float* fw = g_FW + ((size_t)b * TSTEPS + t) * NCOLS;
    float xr = fw[d] + pr + Urb[d];
    float r  = 1.f / (1.f + expf(-xr));
    float up = pu + Ub[d];
    float ht = tanhf(fw[1024 + d] + r * up);
    float gt = g[b * TSTEPS + t];
    float hold = g_h[idx];
    float hn = gt * ht + (1.f - gt) * hold;
    g_h[idx] = hn;

    __nv_bfloat16 hi = __float2bfloat16(hn);
    __nv_bfloat16 lo = __float2bfloat16(hn - __bfloat162float(hi));
    __nv_bfloat16* row = g_Ah + (size_t)b * KP;
    row[d] = hi; row[1024 + d] = hi; row[2048 + d] = lo;

    if (t == nf[b] - 1) out[idx] = hn;
}

// ---------------------------------------------------------------------------
extern "C" void kernel_launch(void* const* d_in, const int* in_sizes, int n_in,
                              void* d_out, int out_size) {
    const float* facts   = (const float*)d_in[0];
    const int*   nf      = (const int*)d_in[1];
    const float* g       = (const float*)d_in[2];
    const float* mem_old = (const float*)d_in[3];
    const float* Wr      = (const float*)d_in[4];
    const float* Urw     = (const float*)d_in[5];
    const float* Urb     = (const float*)d_in[6];
    const float* W       = (const float*)d_in[7];
    const float* Uw      = (const float*)d_in[8];
    const float* Ub      = (const float*)d_in[9];
    float* out = (float*)d_out;

    init_h_kernel<<<(BATCH * DIM) / 256, 256>>>(mem_old);
    pack_w_kernel<<<(2048 * 1024) / 256, 256>>>(Wr, W, /*which=*/0);
    pack_w_kernel<<<(2048 * 1024) / 256, 256>>>(Urw, Uw, /*which=*/1);
    pack_facts_kernel<<<(16384 * 1024) / 256, 256>>>(facts);

    // precompute fWr||fW : [16384, 2048] = A'(facts) @ B'(Wr;W)^T
    gemm_wmma<<<dim3(NCOLS / BN, 128, 1), 128>>>(/*mode=*/0, NCHUNK);

    // sequential scan
    for (int t = 0; t < TSTEPS; ++t) {
        gemm_wmma<<<dim3(NCOLS / BN, 1, KSPLIT), 128>>>(/*mode=*/1,
                                                        NCHUNK / KSPLIT);
        combine_kernel<<<(BATCH * DIM) / 256, 256>>>(g, Urb, Ub, nf, out, t);
    }
}